// round 2
// baseline (speedup 1.0000x reference)
#include <cuda_runtime.h>

#define BB 4
#define TT 512
#define TPQ 1024
#define CC 32
#define KK 128

// Scratch (no allocation allowed in kernel_launch)
__device__ float g_A[CC * CC];      // softplus(alpha)[e][c]
__device__ float g_D[CC * CC];      // softplus(delta)[e][c] + EPS
__device__ float g_spmu[CC];        // softplus(mu)[c]
__device__ float g_fp[KK];          // fine probs
__device__ float g_st[BB * TT];     // per-batch times, grouped by coarse type
__device__ float g_PS[BB * TT * CC];// prefix sums of exp(D[e][c]*t_i) within each (b,e) group
__device__ int   g_off[BB * CC];
__device__ int   g_cnt[BB * CC];

__device__ __forceinline__ float softplus_f(float x) {
    return fmaxf(x, 0.f) + log1pf(expf(-fabsf(x)));
}

// Kernel 1: parameter tables + fine probabilities (one block)
__global__ void prep_kernel(const float* __restrict__ mu,
                            const float* __restrict__ alpha,
                            const float* __restrict__ delta,
                            const float* __restrict__ cf,
                            const int* __restrict__ ftc) {
    int tid = threadIdx.x;
    if (tid < CC * CC) {
        g_A[tid] = softplus_f(alpha[tid]);
        g_D[tid] = softplus_f(delta[tid]) + 2.220446049250313e-16f;
    }
    if (tid < CC) g_spmu[tid] = softplus_f(mu[tid]);

    __shared__ float s_e[KK];
    __shared__ float s_den[CC];
    __shared__ float s_max;
    if (tid == 0) {
        float m = cf[0];
        for (int k = 1; k < KK; k++) m = fmaxf(m, cf[k]);
        s_max = m;
    }
    __syncthreads();
    if (tid < KK) s_e[tid] = expf(cf[tid] - s_max);
    __syncthreads();
    if (tid < CC) {
        // deterministic segment sum
        float d = 0.f;
        for (int k = 0; k < KK; k++)
            if (ftc[k] == tid) d += s_e[k];
        s_den[tid] = d;
    }
    __syncthreads();
    if (tid < KK) g_fp[tid] = s_e[tid] / s_den[ftc[tid]];
}

// Kernel 2: per-batch, group events by coarse type (time order preserved)
__global__ void compact_kernel(const int* __restrict__ pe,
                               const float* __restrict__ pt) {
    int b = blockIdx.x;
    int e = threadIdx.x;  // 0..31, one type per lane
    const int* peb = pe + b * TT;
    const float* ptb = pt + b * TT;
    int cnt = 0;
    for (int i = 0; i < TT; i++) cnt += (peb[i] == e);
    // warp inclusive scan -> exclusive offset
    int incl = cnt;
    #pragma unroll
    for (int d = 1; d < 32; d <<= 1) {
        int v = __shfl_up_sync(0xffffffffu, incl, d);
        if (e >= d) incl += v;
    }
    int off = incl - cnt;
    g_off[b * CC + e] = off;
    g_cnt[b * CC + e] = cnt;
    int p = off;
    for (int i = 0; i < TT; i++) {
        if (peb[i] == e) { g_st[b * TT + p] = ptb[i]; p++; }
    }
}

// Kernel 3: prefix sums of exp(D[e][c] * t_i) within each (b,e) group, per c
__global__ void prefix_kernel() {
    int b = blockIdx.x;
    int e = threadIdx.x >> 5;
    int c = threadIdx.x & 31;
    int off = g_off[b * CC + e];
    int cnt = g_cnt[b * CC + e];
    float D = g_D[e * CC + c];
    float s = 0.f;
    for (int j = 0; j < cnt; j++) {
        s += __expf(D * g_st[b * TT + off + j]);
        g_PS[(size_t)(b * TT + off + j) * CC + c] = s;  // coalesced over c
    }
}

// Kernel 4: one warp per query (b,tp); lane = coarse channel c
__global__ __launch_bounds__(256) void main_kernel(const float* __restrict__ tt,
                                                   const int* __restrict__ ftc,
                                                   float* __restrict__ out) {
    __shared__ float sA[CC * CC], sD[CC * CC], sfp[KK], sspmu[CC];
    __shared__ int sftc[KK];
    int tid = threadIdx.x;
    for (int i = tid; i < CC * CC; i += 256) { sA[i] = g_A[i]; sD[i] = g_D[i]; }
    if (tid < KK) { sfp[tid] = g_fp[tid]; sftc[tid] = ftc[tid]; }
    if (tid < CC) sspmu[tid] = g_spmu[tid];
    __syncthreads();

    int w = blockIdx.x * 8 + (tid >> 5);
    int lane = tid & 31;
    int b = w >> 10;             // TPQ = 1024
    int tp = w & (TPQ - 1);
    float tq = tt[b * TPQ + tp];

    // per-lane binary search in type 'lane' group: count of t_i < tq
    int off = g_off[b * CC + lane];
    int cnt = g_cnt[b * CC + lane];
    const float* st = g_st + b * TT + off;
    int lo = 0, hi = cnt;
    while (lo < hi) {
        int mid = (lo + hi) >> 1;
        if (st[mid] < tq) lo = mid + 1; else hi = mid;
    }
    int jc = lo;

    float acc = 0.f;
    #pragma unroll 4
    for (int e = 0; e < CC; e++) {
        int j = __shfl_sync(0xffffffffu, jc, e);
        if (j > 0) {
            int offe = __shfl_sync(0xffffffffu, off, e);
            float ps = g_PS[(size_t)(b * TT + offe + j - 1) * CC + lane];
            acc = fmaf(sA[e * CC + lane] * __expf(-sD[e * CC + lane] * tq), ps, acc);
        }
    }
    acc += sspmu[lane];

    int base = (b * TPQ + tp) * KK;
    #pragma unroll
    for (int q = 0; q < 4; q++) {
        int k = lane + 32 * q;
        float v = __shfl_sync(0xffffffffu, acc, sftc[k]);
        out[base + k] = v * sfp[k];
    }
}

extern "C" void kernel_launch(void* const* d_in, const int* in_sizes, int n_in,
                              void* d_out, int out_size) {
    const int*   pe    = (const int*)d_in[0];    // past_event [B,T]
    const float* pt    = (const float*)d_in[1];  // past_time  [B,T]
    const float* tt    = (const float*)d_in[2];  // time_tensor [B,TP]
    const float* mu    = (const float*)d_in[3];  // [C]
    const float* alpha = (const float*)d_in[4];  // [C,C]
    const float* delta = (const float*)d_in[5];  // [C,C]
    const float* cf    = (const float*)d_in[6];  // [K]
    const int*   ftc   = (const int*)d_in[7];    // [K]
    float* out = (float*)d_out;

    prep_kernel<<<1, 1024>>>(mu, alpha, delta, cf, ftc);
    compact_kernel<<<BB, 32>>>(pe, pt);
    prefix_kernel<<<BB, 1024>>>();
    main_kernel<<<(BB * TPQ) / 8, 256>>>(tt, ftc, out);
}

// round 3
// speedup vs baseline: 2.3322x; 2.3322x over previous
#include <cuda_runtime.h>

#define BB 4
#define TT 512
#define TPQ 1024
#define CC 32
#define KK 128
#define EPSF 2.220446049250313e-16f

// Scratch (no allocation allowed)
__device__ float g_A[CC * CC];              // softplus(alpha)[e][c]
__device__ float g_D[CC * CC];              // softplus(delta)[e][c] + EPS
__device__ float g_spmu[CC];                // softplus(mu)[c]
__device__ float g_fp[KK];                  // fine probs
__device__ float g_st[BB * TT];             // per-batch times, grouped by coarse type
__device__ float g_PS[(BB * TT + 1) * CC];  // prefix sums + one zero guard row at BB*TT
__device__ int   g_off[BB * CC];
__device__ int   g_cnt[BB * CC];

__device__ __forceinline__ float softplus_f(float x) {
    return fmaxf(x, 0.f) + log1pf(expf(-fabsf(x)));
}

// ---------------------------------------------------------------------------
// Kernel 1: per-batch compaction + prefix sums; block 0 also does param prep.
// grid = BB blocks, 1024 threads. thread tid maps to (e = tid>>5, c = tid&31).
// ---------------------------------------------------------------------------
__global__ __launch_bounds__(1024) void prep_kernel(
    const int* __restrict__ pe, const float* __restrict__ pt,
    const float* __restrict__ mu, const float* __restrict__ alpha,
    const float* __restrict__ delta, const float* __restrict__ cf,
    const int* __restrict__ ftc) {
    __shared__ float s_t[TT];     // raw times
    __shared__ int   s_ev[TT];    // raw events
    __shared__ float s_ct[TT];    // compacted times (grouped by type)
    __shared__ int   s_cnt[CC], s_off[CC];
    __shared__ float s_e[KK];
    __shared__ float s_den[CC];
    __shared__ float s_max;

    int b = blockIdx.x;
    int tid = threadIdx.x;
    int e = tid >> 5;
    int lane = tid & 31;

    // own softplus(delta)+eps — every block computes its own copy (register)
    float Dreg = softplus_f(delta[tid]) + EPSF;

    // block 0: publish parameter tables + fine probs + zero guard row
    if (b == 0) {
        g_A[tid] = softplus_f(alpha[tid]);
        g_D[tid] = Dreg;
        if (tid < CC) g_spmu[tid] = softplus_f(mu[tid]);
        if (tid < CC) g_PS[(size_t)(BB * TT) * CC + tid] = 0.f;
        if (tid == 0) {
            float m = cf[0];
            for (int k = 1; k < KK; k++) m = fmaxf(m, cf[k]);
            s_max = m;
        }
    }

    // load this batch's events/times into smem
    if (tid < TT) { s_t[tid] = pt[b * TT + tid]; s_ev[tid] = pe[b * TT + tid]; }
    __syncthreads();

    if (b == 0) {
        if (tid < KK) s_e[tid] = expf(cf[tid] - s_max);
    }

    // pass 1: warp e counts events of type e via ballot
    unsigned cnt = 0;
    #pragma unroll
    for (int it = 0; it < TT / 32; it++) {
        unsigned m = __ballot_sync(0xffffffffu, s_ev[it * 32 + lane] == e);
        cnt += __popc(m);
    }
    if (lane == 0) s_cnt[e] = (int)cnt;
    __syncthreads();

    if (b == 0) {
        if (tid < CC) {
            float d = 0.f;
            for (int k = 0; k < KK; k++)
                if (ftc[k] == tid) d += s_e[k];
            s_den[tid] = d;
        }
    }

    // exclusive scan of the 32 counts (warp 0)
    if (e == 0) {
        int v = s_cnt[lane];
        int incl = v;
        #pragma unroll
        for (int d = 1; d < 32; d <<= 1) {
            int u = __shfl_up_sync(0xffffffffu, incl, d);
            if (lane >= d) incl += u;
        }
        s_off[lane] = incl - v;
        g_off[b * CC + lane] = incl - v;
        g_cnt[b * CC + lane] = v;
    }
    __syncthreads();

    if (b == 0 && tid < KK) g_fp[tid] = s_e[tid] / s_den[ftc[tid]];

    // pass 2: stable stream compaction of type-e times (warp e)
    {
        int pos = s_off[e];
        #pragma unroll
        for (int it = 0; it < TT / 32; it++) {
            int i = it * 32 + lane;
            bool hit = (s_ev[i] == e);
            unsigned m = __ballot_sync(0xffffffffu, hit);
            if (hit) {
                int rank = __popc(m & ((1u << lane) - 1u));
                float tv = s_t[i];
                s_ct[pos + rank] = tv;
                g_st[b * TT + pos + rank] = tv;
            }
            pos += __popc(m);
        }
    }
    __syncthreads();

    // prefix sums: thread (e, c) walks group e serially
    {
        int off = s_off[e];
        int n = s_cnt[e];
        float s = 0.f;
        for (int j = 0; j < n; j++) {
            s += __expf(Dreg * s_ct[off + j]);           // smem broadcast
            g_PS[(size_t)(b * TT + off + j) * CC + lane] = s;  // coalesced over c
        }
    }
}

// ---------------------------------------------------------------------------
// Kernel 2: one warp per query (b,tp); lane = coarse channel c.
// Branch-free inner loop via guard row in g_PS.
// ---------------------------------------------------------------------------
__global__ __launch_bounds__(256) void main_kernel(const float* __restrict__ tt,
                                                   const int* __restrict__ ftc,
                                                   float* __restrict__ out) {
    __shared__ float sA[CC * CC], sD[CC * CC], sfp[KK], sspmu[CC];
    __shared__ int sftc[KK];
    __shared__ int srow[8][CC];  // per-warp resolved PS row indices
    int tid = threadIdx.x;
    for (int i = tid; i < CC * CC; i += 256) { sA[i] = g_A[i]; sD[i] = g_D[i]; }
    if (tid < KK) { sfp[tid] = g_fp[tid]; sftc[tid] = ftc[tid]; }
    if (tid < CC) sspmu[tid] = g_spmu[tid];
    __syncthreads();

    int wslot = tid >> 5;
    int w = blockIdx.x * 8 + wslot;
    int lane = tid & 31;
    int b = w >> 10;             // TPQ = 1024
    int tp = w & (TPQ - 1);
    float tq = tt[b * TPQ + tp];

    // per-lane binary search in its own type group: j = #{t_i < tq}
    int off = g_off[b * CC + lane];
    int cnt = g_cnt[b * CC + lane];
    const float* st = g_st + b * TT + off;
    int lo = 0, hi = cnt;
    while (lo < hi) {
        int mid = (lo + hi) >> 1;
        if (st[mid] < tq) lo = mid + 1; else hi = mid;
    }
    // resolved PS row (guard row = BB*TT holds zeros -> contributes 0)
    int row = (lo > 0) ? (b * TT + off + lo - 1) : (BB * TT);
    srow[wslot][lane] = row;
    __syncwarp();

    float acc = 0.f;
    #pragma unroll 8
    for (int e = 0; e < CC; e++) {
        int r = srow[wslot][e];
        float ps = g_PS[(size_t)r * CC + lane];                  // coalesced 128B
        acc = fmaf(sA[e * CC + lane] * __expf(-sD[e * CC + lane] * tq), ps, acc);
    }
    acc += sspmu[lane];

    int base = (b * TPQ + tp) * KK;
    #pragma unroll
    for (int q = 0; q < 4; q++) {
        int k = lane + 32 * q;
        float v = __shfl_sync(0xffffffffu, acc, sftc[k]);
        out[base + k] = v * sfp[k];
    }
}

extern "C" void kernel_launch(void* const* d_in, const int* in_sizes, int n_in,
                              void* d_out, int out_size) {
    const int*   pe    = (const int*)d_in[0];    // past_event [B,T]
    const float* pt    = (const float*)d_in[1];  // past_time  [B,T]
    const float* tt    = (const float*)d_in[2];  // time_tensor [B,TP]
    const float* mu    = (const float*)d_in[3];  // [C]
    const float* alpha = (const float*)d_in[4];  // [C,C]
    const float* delta = (const float*)d_in[5];  // [C,C]
    const float* cf    = (const float*)d_in[6];  // [K]
    const int*   ftc   = (const int*)d_in[7];    // [K]
    float* out = (float*)d_out;

    prep_kernel<<<BB, 1024>>>(pe, pt, mu, alpha, delta, cf, ftc);
    main_kernel<<<(BB * TPQ) / 8, 256>>>(tt, ftc, out);
}

// round 4
// speedup vs baseline: 3.5450x; 1.5200x over previous
#include <cuda_runtime.h>

#define BB 4
#define TT 512
#define TPQ 1024
#define CC 32
#define KK 128
#define EPSF 2.220446049250313e-16f
#define NBLK 128
#define QPB ((BB * TPQ) / NBLK)   // 32 queries per block
#define NW 8                      // warps per block (256 threads)
#define QPW (QPB / NW)            // 4 queries per warp

__device__ __forceinline__ float softplus_f(float x) {
    return fmaxf(x, 0.f) + log1pf(__expf(-fabsf(x)));
}

__global__ void __launch_bounds__(256, 1) fused_kernel(
    const int* __restrict__ pe, const float* __restrict__ pt,
    const float* __restrict__ tt,
    const float* __restrict__ mu, const float* __restrict__ alpha,
    const float* __restrict__ delta, const float* __restrict__ cf,
    const int* __restrict__ ftc, float* __restrict__ out)
{
    extern __shared__ float sPS[];      // (TT+1)*CC floats; row TT = zero guard
    __shared__ float2 sAD[CC * CC];     // (softplus(alpha), softplus(delta)+eps)
    __shared__ float  s_ct[TT];         // compacted times (grouped by type)
    __shared__ float  s_t[TT];
    __shared__ int    s_ev[TT];
    __shared__ float  sfp[KK], s_e[KK], s_cf[KK];
    __shared__ float  s_den[CC], sspmu[CC];
    __shared__ int    sftc[KK];
    __shared__ int    s_cnt[CC], s_off[CC];
    __shared__ float  s_max;
    __shared__ int    s_row[NW][QPW][CC];

    const int tid  = threadIdx.x;
    const int w    = tid >> 5;
    const int lane = tid & 31;
    const int b    = blockIdx.x >> 5;        // 32 blocks per batch
    const int qbase = blockIdx.x * QPB;      // flattened b*TPQ + tp base

    // ---- Phase A: load raw data + parameter tables ----
    for (int i = tid; i < TT; i += 256) {
        s_t[i]  = pt[b * TT + i];
        s_ev[i] = pe[b * TT + i];
    }
    for (int i = tid; i < CC * CC; i += 256) {
        sAD[i] = make_float2(softplus_f(alpha[i]), softplus_f(delta[i]) + EPSF);
    }
    if (tid < KK) { s_cf[tid] = cf[tid]; sftc[tid] = ftc[tid]; }
    if (tid < CC) sspmu[tid] = softplus_f(mu[tid]);
    if (tid < CC) sPS[TT * CC + tid] = 0.f;   // guard row
    __syncthreads();

    // ---- Phase B: count events per type (warp w -> types w, w+8, ...) ----
    for (int eo = w; eo < CC; eo += NW) {
        unsigned cnt = 0;
        #pragma unroll
        for (int it = 0; it < TT / 32; it++)
            cnt += __popc(__ballot_sync(0xffffffffu, s_ev[it * 32 + lane] == eo));
        if (lane == 0) s_cnt[eo] = (int)cnt;
    }
    __syncthreads();

    // warp 0: exclusive scan of counts; warp 1: max(cf)
    if (w == 0) {
        int v = s_cnt[lane];
        int incl = v;
        #pragma unroll
        for (int d = 1; d < 32; d <<= 1) {
            int u = __shfl_up_sync(0xffffffffu, incl, d);
            if (lane >= d) incl += u;
        }
        s_off[lane] = incl - v;
    }
    if (w == 1) {
        float m = fmaxf(fmaxf(s_cf[lane], s_cf[lane + 32]),
                        fmaxf(s_cf[lane + 64], s_cf[lane + 96]));
        #pragma unroll
        for (int d = 16; d > 0; d >>= 1)
            m = fmaxf(m, __shfl_xor_sync(0xffffffffu, m, d));
        if (lane == 0) s_max = m;
    }
    __syncthreads();

    // ---- Phase C: stable compaction + exp of logits ----
    if (tid < KK) s_e[tid] = __expf(s_cf[tid] - s_max);
    for (int eo = w; eo < CC; eo += NW) {
        int pos = s_off[eo];
        #pragma unroll
        for (int it = 0; it < TT / 32; it++) {
            int i = it * 32 + lane;
            bool hit = (s_ev[i] == eo);
            unsigned m = __ballot_sync(0xffffffffu, hit);
            if (hit) {
                int rank = __popc(m & ((1u << lane) - 1u));
                s_ct[pos + rank] = s_t[i];
            }
            pos += __popc(m);
        }
    }
    __syncthreads();

    // ---- Phase D: prefix sums into sPS + fine-prob denominators ----
    if (tid < CC) {
        float dsum = 0.f;
        for (int k = 0; k < KK; k++)
            if (sftc[k] == tid) dsum += s_e[k];
        s_den[tid] = dsum;
    }
    #pragma unroll
    for (int r = 0; r < 4; r++) {
        int p = tid + 256 * r;           // (e,c) pair
        int e = p >> 5, c = p & 31;
        int off = s_off[e], n = s_cnt[e];
        float D = sAD[e * CC + c].y;
        float s = 0.f;
        for (int j = 0; j < n; j++) {
            s += __expf(D * s_ct[off + j]);
            sPS[(off + j) * CC + c] = s;     // conflict-free over c
        }
    }
    __syncthreads();
    if (tid < KK) sfp[tid] = s_e[tid] / s_den[sftc[tid]];
    __syncthreads();

    // ---- Phase E: queries. Warp w handles 4 queries; lane = coarse channel ----
    const int off_l = s_off[lane];
    const int cnt_l = s_cnt[lane];
    float tq[QPW];
    #pragma unroll
    for (int q = 0; q < QPW; q++) {
        int qi = qbase + w * QPW + q;
        tq[q] = tt[qi];
        int lo = 0, hi = cnt_l;
        while (lo < hi) {
            int mid = (lo + hi) >> 1;
            if (s_ct[off_l + mid] < tq[q]) lo = mid + 1; else hi = mid;
        }
        s_row[w][q][lane] = (lo > 0) ? (off_l + lo - 1) : TT;
    }
    __syncwarp();

    float acc[QPW] = {0.f, 0.f, 0.f, 0.f};
    #pragma unroll 8
    for (int e = 0; e < CC; e++) {
        float2 ad = sAD[e * CC + lane];
        #pragma unroll
        for (int q = 0; q < QPW; q++) {
            int r = s_row[w][q][e];            // broadcast LDS
            float ps = sPS[r * CC + lane];     // conflict-free 128B
            acc[q] = fmaf(ad.x * __expf(-ad.y * tq[q]), ps, acc[q]);
        }
    }
    #pragma unroll
    for (int q = 0; q < QPW; q++) acc[q] += sspmu[lane];

    #pragma unroll
    for (int q = 0; q < QPW; q++) {
        size_t base = (size_t)(qbase + w * QPW + q) * KK;
        #pragma unroll
        for (int s4 = 0; s4 < 4; s4++) {
            int k = lane + 32 * s4;
            float v = __shfl_sync(0xffffffffu, acc[q], sftc[k]);
            out[base + k] = v * sfp[k];
        }
    }
}

extern "C" void kernel_launch(void* const* d_in, const int* in_sizes, int n_in,
                              void* d_out, int out_size) {
    const int*   pe    = (const int*)d_in[0];
    const float* pt    = (const float*)d_in[1];
    const float* tt    = (const float*)d_in[2];
    const float* mu    = (const float*)d_in[3];
    const float* alpha = (const float*)d_in[4];
    const float* delta = (const float*)d_in[5];
    const float* cf    = (const float*)d_in[6];
    const int*   ftc   = (const int*)d_in[7];
    float* out = (float*)d_out;

    const int dyn_smem = (TT + 1) * CC * (int)sizeof(float);  // 65,664 B
    cudaFuncSetAttribute(fused_kernel,
                         cudaFuncAttributeMaxDynamicSharedMemorySize, dyn_smem);
    fused_kernel<<<NBLK, 256, dyn_smem>>>(pe, pt, tt, mu, alpha, delta, cf, ftc, out);
}

// round 5
// speedup vs baseline: 3.5990x; 1.0152x over previous
#include <cuda_runtime.h>

#define BB 4
#define TT 512
#define TPQ 1024
#define CC 32
#define KK 128
#define EPSF 2.220446049250313e-16f

// Scratch
__device__ float2 g_AD[CC * CC];            // (softplus(alpha), softplus(delta)+eps)
__device__ float  g_spmu[CC];
__device__ float  g_fp[KK];
__device__ float  g_st[BB * TT];            // per-batch times grouped by type
__device__ float  g_PS[(BB * TT + 1) * CC]; // prefix sums + zero guard row at BB*TT
__device__ int    g_off[BB * CC];
__device__ int    g_cnt[BB * CC];

__device__ __forceinline__ float softplus_f(float x) {
    return fmaxf(x, 0.f) + log1pf(__expf(-fabsf(x)));
}

// ---------------------------------------------------------------------------
// Kernel 1: per-batch compaction + prefix-sum table; block 0 also does params.
// grid = BB, 1024 threads; thread tid = (e = tid>>5, c = tid&31)
// ---------------------------------------------------------------------------
__global__ __launch_bounds__(1024) void prep_kernel(
    const int* __restrict__ pe, const float* __restrict__ pt,
    const float* __restrict__ mu, const float* __restrict__ alpha,
    const float* __restrict__ delta, const float* __restrict__ cf,
    const int* __restrict__ ftc) {
    __shared__ float s_t[TT];
    __shared__ int   s_ev[TT];
    __shared__ float s_ct[TT];
    __shared__ int   s_cnt[CC], s_off[CC];
    __shared__ float s_e[KK];
    __shared__ float s_den[CC];
    __shared__ float s_max;

    int b = blockIdx.x;
    int tid = threadIdx.x;
    int e = tid >> 5;
    int lane = tid & 31;

    float Dreg = softplus_f(delta[tid]) + EPSF;

    if (b == 0) {
        g_AD[tid] = make_float2(softplus_f(alpha[tid]), Dreg);
        if (tid < CC) g_spmu[tid] = softplus_f(mu[tid]);
        if (tid < CC) g_PS[(size_t)(BB * TT) * CC + tid] = 0.f;
        if (tid == 0) {
            float m = cf[0];
            for (int k = 1; k < KK; k++) m = fmaxf(m, cf[k]);
            s_max = m;
        }
    }

    if (tid < TT) { s_t[tid] = pt[b * TT + tid]; s_ev[tid] = pe[b * TT + tid]; }
    __syncthreads();

    if (b == 0 && tid < KK) s_e[tid] = expf(cf[tid] - s_max);

    // count per type (warp e)
    unsigned cnt = 0;
    #pragma unroll
    for (int it = 0; it < TT / 32; it++)
        cnt += __popc(__ballot_sync(0xffffffffu, s_ev[it * 32 + lane] == e));
    if (lane == 0) s_cnt[e] = (int)cnt;
    __syncthreads();

    if (b == 0 && tid < CC) {
        float d = 0.f;
        for (int k = 0; k < KK; k++)
            if (ftc[k] == tid) d += s_e[k];
        s_den[tid] = d;
    }

    if (e == 0) {  // exclusive scan of counts
        int v = s_cnt[lane];
        int incl = v;
        #pragma unroll
        for (int d = 1; d < 32; d <<= 1) {
            int u = __shfl_up_sync(0xffffffffu, incl, d);
            if (lane >= d) incl += u;
        }
        s_off[lane] = incl - v;
        g_off[b * CC + lane] = incl - v;
        g_cnt[b * CC + lane] = v;
    }
    __syncthreads();

    if (b == 0 && tid < KK) g_fp[tid] = s_e[tid] / s_den[ftc[tid]];

    // stable compaction (warp e)
    {
        int pos = s_off[e];
        #pragma unroll
        for (int it = 0; it < TT / 32; it++) {
            int i = it * 32 + lane;
            bool hit = (s_ev[i] == e);
            unsigned m = __ballot_sync(0xffffffffu, hit);
            if (hit) {
                int rank = __popc(m & ((1u << lane) - 1u));
                float tv = s_t[i];
                s_ct[pos + rank] = tv;
                g_st[b * TT + pos + rank] = tv;
            }
            pos += __popc(m);
        }
    }
    __syncthreads();

    // prefix sums: thread (e,c) walks group e
    {
        int off = s_off[e];
        int n = s_cnt[e];
        float s = 0.f;
        for (int j = 0; j < n; j++) {
            s += __expf(Dreg * s_ct[off + j]);
            g_PS[(size_t)(b * TT + off + j) * CC + lane] = s;
        }
    }
}

// ---------------------------------------------------------------------------
// Kernel 2: queries. Block = 256 threads = 8 warps = 4 queries (2 warps each).
// Warp pair halves split the e-loop; partials combined via smem.
// ---------------------------------------------------------------------------
__global__ __launch_bounds__(256, 4) void query_kernel(
    const float* __restrict__ tt, const int* __restrict__ ftc,
    float* __restrict__ out) {
    __shared__ float2 sAD[CC * CC];
    __shared__ float  sfp[KK], sspmu[CC];
    __shared__ int    sftc[KK];
    __shared__ int    s_row[4][CC];
    __shared__ float  s_acc[4][2][CC];

    const int tid = threadIdx.x;
    const int w = tid >> 5;
    const int lane = tid & 31;
    const int qbase = blockIdx.x * 4;      // 4 queries, same batch (TPQ%4==0)
    const int b = qbase >> 10;             // TPQ = 1024

    #pragma unroll
    for (int i = tid; i < CC * CC; i += 256) sAD[i] = g_AD[i];
    if (tid < KK) { sfp[tid] = g_fp[tid]; sftc[tid] = ftc[tid]; }
    if (tid < CC) sspmu[tid] = g_spmu[tid];

    // warps 0..3: binary search for query w (lane = type)
    if (w < 4) {
        float tqs = tt[qbase + w];
        int off = g_off[b * CC + lane];
        int cnt = g_cnt[b * CC + lane];
        const float* st = g_st + b * TT + off;
        int lo = 0, hi = cnt;
        while (lo < hi) {
            int mid = (lo + hi) >> 1;
            if (st[mid] < tqs) lo = mid + 1; else hi = mid;
        }
        s_row[w][lane] = (lo > 0) ? (b * TT + off + lo - 1) : (BB * TT);
    }
    __syncthreads();

    const int q = w >> 1;
    const int h = w & 1;
    const float tq = tt[qbase + q];

    float acc = 0.f;
    #pragma unroll
    for (int i = 0; i < 16; i++) {
        int e = h * 16 + i;
        float2 ad = sAD[e * CC + lane];
        float ps = g_PS[(size_t)s_row[q][e] * CC + lane];   // L2-resident, MLP=16
        acc = fmaf(ad.x * __expf(-ad.y * tq), ps, acc);
    }
    s_acc[q][h][lane] = acc;
    __syncthreads();

    // epilogue: warp w -> query (w>>1), k-range (w&1)*64 .. +64 (coalesced)
    {
        int qq = w >> 1;
        size_t base = (size_t)(qbase + qq) * KK;
        #pragma unroll
        for (int s = 0; s < 2; s++) {
            int k = (w & 1) * 64 + s * 32 + lane;
            int c = sftc[k];
            float v = (s_acc[qq][0][c] + s_acc[qq][1][c] + sspmu[c]) * sfp[k];
            out[base + k] = v;
        }
    }
}

extern "C" void kernel_launch(void* const* d_in, const int* in_sizes, int n_in,
                              void* d_out, int out_size) {
    const int*   pe    = (const int*)d_in[0];
    const float* pt    = (const float*)d_in[1];
    const float* tt    = (const float*)d_in[2];
    const float* mu    = (const float*)d_in[3];
    const float* alpha = (const float*)d_in[4];
    const float* delta = (const float*)d_in[5];
    const float* cf    = (const float*)d_in[6];
    const int*   ftc   = (const int*)d_in[7];
    float* out = (float*)d_out;

    prep_kernel<<<BB, 1024>>>(pe, pt, mu, alpha, delta, cf, ftc);
    query_kernel<<<(BB * TPQ) / 4, 256>>>(tt, ftc, out);
}

// round 7
// speedup vs baseline: 3.6863x; 1.0243x over previous
#include <cuda_runtime.h>

#define BB 4
#define TT 512
#define TPQ 1024
#define CC 32
#define KK 128
#define EPSF 2.220446049250313e-16f

// Scratch
__device__ float2 g_AD[CC * CC];            // (softplus(alpha), softplus(delta)+eps)
__device__ float  g_spmu[CC];
__device__ float  g_fp[KK];
__device__ float  g_st[BB * TT];            // per-batch times grouped by type
__device__ float  g_PS[(BB * TT + 1) * CC]; // prefix sums + zero guard row at BB*TT
__device__ int    g_off[BB * CC];
__device__ int    g_cnt[BB * CC];

__device__ __forceinline__ float softplus_f(float x) {
    return fmaxf(x, 0.f) + log1pf(__expf(-fabsf(x)));
}

// ---------------------------------------------------------------------------
// Kernel 1: prep, 16 blocks (4 per batch; each owns 8 coarse types), 256 thr.
// Block 0 additionally publishes parameter tables + fine probs + guard row.
// ---------------------------------------------------------------------------
__global__ __launch_bounds__(256) void prep_kernel(
    const int* __restrict__ pe, const float* __restrict__ pt,
    const float* __restrict__ mu, const float* __restrict__ alpha,
    const float* __restrict__ delta, const float* __restrict__ cf,
    const int* __restrict__ ftc) {
    __shared__ float s_t[TT];
    __shared__ int   s_ev[TT];
    __shared__ float s_ct[TT];       // only own-type ranges filled
    __shared__ int   s_cnt[CC], s_off[CC];
    __shared__ float s_e[KK];
    __shared__ float s_den[CC];
    __shared__ float s_max;

    const int tid  = threadIdx.x;
    const int w    = tid >> 5;
    const int lane = tid & 31;
    const int b    = blockIdx.x >> 2;        // batch
    const int tg   = (blockIdx.x & 3) * 8;   // this block's type base
    const int ty   = tg + w;                 // warp w's type

    // load batch events/times
    for (int i = tid; i < TT; i += 256) {
        s_t[i]  = pt[b * TT + i];
        s_ev[i] = pe[b * TT + i];
    }
    // block 0: max(cf) via warp 7 (independent of event data)
    if (blockIdx.x == 0 && w == 7) {
        float m = fmaxf(fmaxf(cf[lane], cf[lane + 32]),
                        fmaxf(cf[lane + 64], cf[lane + 96]));
        #pragma unroll
        for (int d = 16; d > 0; d >>= 1)
            m = fmaxf(m, __shfl_xor_sync(0xffffffffu, m, d));
        if (lane == 0) s_max = m;
    }
    __syncthreads();

    // counts: warp w counts types w, w+8, w+16, w+24
    #pragma unroll
    for (int r = 0; r < 4; r++) {
        int t = w + 8 * r;
        unsigned cnt = 0;
        #pragma unroll
        for (int it = 0; it < TT / 32; it++)
            cnt += __popc(__ballot_sync(0xffffffffu, s_ev[it * 32 + lane] == t));
        if (lane == 0) s_cnt[t] = (int)cnt;
    }
    // block 0 param prep (independent)
    if (blockIdx.x == 0) {
        #pragma unroll
        for (int r = 0; r < 4; r++) {
            int i = tid + 256 * r;
            g_AD[i] = make_float2(softplus_f(alpha[i]), softplus_f(delta[i]) + EPSF);
        }
        if (tid < CC) g_spmu[tid] = softplus_f(mu[tid]);
        if (tid < CC) g_PS[(size_t)(BB * TT) * CC + tid] = 0.f;
        if (tid < KK) s_e[tid] = expf(cf[tid] - s_max);
    }
    __syncthreads();

    // warp 0: exclusive scan of the 32 counts
    if (w == 0) {
        int v = s_cnt[lane];
        int incl = v;
        #pragma unroll
        for (int d = 1; d < 32; d <<= 1) {
            int u = __shfl_up_sync(0xffffffffu, incl, d);
            if (lane >= d) incl += u;
        }
        s_off[lane] = incl - v;
        if ((blockIdx.x & 3) == 0) {
            g_off[b * CC + lane] = incl - v;
            g_cnt[b * CC + lane] = v;
        }
    }
    if (blockIdx.x == 0 && tid < CC) {
        float d = 0.f;
        for (int k = 0; k < KK; k++)
            if (ftc[k] == tid) d += s_e[k];
        s_den[tid] = d;
    }
    __syncthreads();

    if (blockIdx.x == 0 && tid < KK) g_fp[tid] = s_e[tid] / s_den[ftc[tid]];

    // stable compaction of this block's 8 types (warp w -> type ty)
    {
        int pos = s_off[ty];
        #pragma unroll
        for (int it = 0; it < TT / 32; it++) {
            int i = it * 32 + lane;
            bool hit = (s_ev[i] == ty);
            unsigned m = __ballot_sync(0xffffffffu, hit);
            if (hit) {
                int rank = __popc(m & ((1u << lane) - 1u));
                float tv = s_t[i];
                s_ct[pos + rank] = tv;
                g_st[b * TT + pos + rank] = tv;
            }
            pos += __popc(m);
        }
    }
    __syncwarp();

    // prefix sums: thread (w, lane) = (type ty, channel lane)
    {
        int off = s_off[ty];
        int n   = s_cnt[ty];
        float D = softplus_f(delta[ty * CC + lane]) + EPSF;
        float s = 0.f;
        for (int j = 0; j < n; j++) {
            s += __expf(D * s_ct[off + j]);
            g_PS[(size_t)(b * TT + off + j) * CC + lane] = s;
        }
    }
}

// ---------------------------------------------------------------------------
// Kernel 2: queries. 1024 blocks x 256 thr; 4 queries/block, 2 warps/query.
// Binary search runs entirely on SMEM.
// ---------------------------------------------------------------------------
__global__ __launch_bounds__(256, 5) void query_kernel(
    const float* __restrict__ tt, const int* __restrict__ ftc,
    float* __restrict__ out) {
    __shared__ float2 sAD[CC * CC];     // 8KB
    __shared__ float  s_st[TT];         // 2KB: this batch's grouped times
    __shared__ float  sfp[KK], sspmu[CC];
    __shared__ int    sftc[KK];
    __shared__ int    s_off[CC], s_cnt[CC];
    __shared__ int    s_row[4][CC];
    __shared__ float  s_acc[4][2][CC];

    const int tid  = threadIdx.x;
    const int w    = tid >> 5;
    const int lane = tid & 31;
    const int qbase = blockIdx.x * 4;   // 4 queries, same batch
    const int b    = qbase >> 10;       // TPQ = 1024

    #pragma unroll
    for (int i = tid; i < CC * CC; i += 256) sAD[i] = g_AD[i];
    #pragma unroll
    for (int i = tid; i < TT; i += 256) s_st[i] = g_st[b * TT + i];
    if (tid < KK) { sfp[tid] = g_fp[tid]; sftc[tid] = ftc[tid]; }
    if (tid < CC) {
        sspmu[tid] = g_spmu[tid];
        s_off[tid] = g_off[b * CC + tid];
        s_cnt[tid] = g_cnt[b * CC + tid];
    }
    __syncthreads();

    // warps 0..3: binary search for query w, lane = type (all LDS)
    if (w < 4) {
        float tqs = tt[qbase + w];
        int off = s_off[lane];
        int lo = 0, hi = s_cnt[lane];
        while (lo < hi) {
            int mid = (lo + hi) >> 1;
            if (s_st[off + mid] < tqs) lo = mid + 1; else hi = mid;
        }
        s_row[w][lane] = (lo > 0) ? (b * TT + off + lo - 1) : (BB * TT);
    }
    __syncthreads();

    const int q = w >> 1;
    const int h = w & 1;
    const float tq = tt[qbase + q];

    float acc = 0.f;
    #pragma unroll
    for (int i = 0; i < 16; i++) {
        int e = h * 16 + i;
        float2 ad = sAD[e * CC + lane];
        float ps = g_PS[(size_t)s_row[q][e] * CC + lane];   // L2-resident, MLP=16
        acc = fmaf(ad.x * __expf(-ad.y * tq), ps, acc);
    }
    s_acc[q][h][lane] = acc;
    __syncthreads();

    // epilogue: warp w -> query w>>1, k-half w&1 (coalesced stores)
    {
        int qq = w >> 1;
        size_t base = (size_t)(qbase + qq) * KK;
        #pragma unroll
        for (int s = 0; s < 2; s++) {
            int k = (w & 1) * 64 + s * 32 + lane;
            int c = sftc[k];
            out[base + k] = (s_acc[qq][0][c] + s_acc[qq][1][c] + sspmu[c]) * sfp[k];
        }
    }
}

extern "C" void kernel_launch(void* const* d_in, const int* in_sizes, int n_in,
                              void* d_out, int out_size) {
    const int*   pe    = (const int*)d_in[0];
    const float* pt    = (const float*)d_in[1];
    const float* tt    = (const float*)d_in[2];
    const float* mu    = (const float*)d_in[3];
    const float* alpha = (const float*)d_in[4];
    const float* delta = (const float*)d_in[5];
    const float* cf    = (const float*)d_in[6];
    const int*   ftc   = (const int*)d_in[7];
    float* out = (float*)d_out;

    prep_kernel<<<BB * 4, 256>>>(pe, pt, mu, alpha, delta, cf, ftc);
    query_kernel<<<(BB * TPQ) / 4, 256>>>(tt, ftc, out);
}